// round 2
// baseline (speedup 1.0000x reference)
#include <cuda_runtime.h>

#define N_NODES 100000
#define N_EDGES 1600000
#define HID 64
#define SCAN_CHUNK 1024
#define SCAN_BLOCKS ((N_NODES + SCAN_CHUNK - 1) / SCAN_CHUNK)  // 98
#define FULL 0xffffffffu

// -------- scratch (static device globals; no runtime allocation) --------
__device__ int   g_deg[N_NODES];
__device__ int   g_cursor[N_NODES];
__device__ int   g_rowoff[N_NODES + 1];
__device__ int   g_psum[SCAN_BLOCKS];
__device__ int   g_csr[N_EDGES];
__device__ float g_dinv[N_NODES];
__device__ float g_h1[(size_t)N_NODES * HID];
__device__ int   g_i64;  // 1 if edge_index is int64, 0 if int32

// -------- dtype detection: int64 values < 2^31 have zero high words --------
__global__ void k_detect(const void* ei) {
    const int* p = (const int*)ei;
    int t = threadIdx.x;                     // 1024 threads, 1 block
    int v = p[2 * t + 1];                    // high word if int64; random id if int32
    int any = __syncthreads_or(v != 0);
    if (t == 0) g_i64 = any ? 0 : 1;
}

__device__ __forceinline__ int load_idx(const void* ei, long long pos, int is64) {
    if (is64) return (int)((const long long*)ei)[pos];
    return ((const int*)ei)[pos];
}

__global__ void k_zero() {
    int i = blockIdx.x * blockDim.x + threadIdx.x;
    int stride = gridDim.x * blockDim.x;
    for (int n = i; n < N_NODES; n += stride) { g_deg[n] = 0; g_cursor[n] = 0; }
}

__global__ void k_deg(const void* __restrict__ ei) {
    int is64 = g_i64;
    int i = blockIdx.x * blockDim.x + threadIdx.x;
    int stride = gridDim.x * blockDim.x;
    for (int e = i; e < N_EDGES; e += stride) {
        int d = load_idx(ei, (long long)N_EDGES + e, is64);
        atomicAdd(&g_deg[d], 1);
    }
}

__global__ void k_dinv() {
    int i = blockIdx.x * blockDim.x + threadIdx.x;
    int stride = gridDim.x * blockDim.x;
    for (int n = i; n < N_NODES; n += stride)
        g_dinv[n] = rsqrtf((float)(g_deg[n] + 1));   // +1 self loop
}

// -------- exclusive scan of g_deg -> g_rowoff --------
__global__ void k_scan_local() {
    __shared__ int sm[SCAN_CHUNK];
    int t = threadIdx.x;
    int idx = blockIdx.x * SCAN_CHUNK + t;
    int v = (idx < N_NODES) ? g_deg[idx] : 0;
    sm[t] = v;
    __syncthreads();
    for (int o = 1; o < SCAN_CHUNK; o <<= 1) {
        int add = (t >= o) ? sm[t - o] : 0;
        __syncthreads();
        sm[t] += add;
        __syncthreads();
    }
    if (idx < N_NODES) g_rowoff[idx] = sm[t] - v;      // exclusive, block-local
    if (t == SCAN_CHUNK - 1) g_psum[blockIdx.x] = sm[t];
}

__global__ void k_scan_top() {   // 1 block, 128 threads (SCAN_BLOCKS=98)
    __shared__ int sm[128];
    int t = threadIdx.x;
    int v = (t < SCAN_BLOCKS) ? g_psum[t] : 0;
    sm[t] = v;
    __syncthreads();
    for (int o = 1; o < 128; o <<= 1) {
        int add = (t >= o) ? sm[t - o] : 0;
        __syncthreads();
        sm[t] += add;
        __syncthreads();
    }
    if (t < SCAN_BLOCKS) g_psum[t] = sm[t] - v;        // exclusive block offsets
    if (t == 127) g_rowoff[N_NODES] = sm[127];         // total = N_EDGES
}

__global__ void k_scan_add() {
    int i = blockIdx.x * blockDim.x + threadIdx.x;
    int stride = gridDim.x * blockDim.x;
    for (int n = i; n < N_NODES; n += stride)
        g_rowoff[n] += g_psum[n / SCAN_CHUNK];
}

__global__ void k_scatter(const void* __restrict__ ei) {
    int is64 = g_i64;
    int i = blockIdx.x * blockDim.x + threadIdx.x;
    int stride = gridDim.x * blockDim.x;
    for (int e = i; e < N_EDGES; e += stride) {
        int s = load_idx(ei, e, is64);
        int d = load_idx(ei, (long long)N_EDGES + e, is64);
        int pos = g_rowoff[d] + atomicAdd(&g_cursor[d], 1);
        g_csr[pos] = s;
    }
}

// -------- layer 1: aggregate 4-dim x, then 4x64 transform + ReLU --------
// warp per node; lanes split edges; outputs j = lane, lane+32
__global__ void k_layer1(const float* __restrict__ x,
                         const float* __restrict__ W1,
                         const float* __restrict__ b1) {
    __shared__ float sW[4 * HID];
    int t = threadIdx.x;                 // 256 threads
    sW[t] = W1[t];
    __syncthreads();
    int warp = (blockIdx.x * blockDim.x + t) >> 5;
    int lane = t & 31;
    if (warp >= N_NODES) return;
    int d = warp;
    int beg = g_rowoff[d], end = g_rowoff[d + 1];
    const float4* x4 = (const float4*)x;
    float a0 = 0.f, a1 = 0.f, a2 = 0.f, a3 = 0.f;
    for (int i = beg + lane; i < end; i += 32) {
        int s = g_csr[i];
        float w = g_dinv[s];
        float4 v = x4[s];
        a0 = fmaf(w, v.x, a0); a1 = fmaf(w, v.y, a1);
        a2 = fmaf(w, v.z, a2); a3 = fmaf(w, v.w, a3);
    }
#pragma unroll
    for (int o = 16; o; o >>= 1) {
        a0 += __shfl_xor_sync(FULL, a0, o);
        a1 += __shfl_xor_sync(FULL, a1, o);
        a2 += __shfl_xor_sync(FULL, a2, o);
        a3 += __shfl_xor_sync(FULL, a3, o);
    }
    float dd = g_dinv[d];
    float4 vd = x4[d];
    a0 = dd * fmaf(dd, vd.x, a0);
    a1 = dd * fmaf(dd, vd.y, a1);
    a2 = dd * fmaf(dd, vd.z, a2);
    a3 = dd * fmaf(dd, vd.w, a3);
    int j0 = lane, j1 = lane + 32;
    float o0 = b1[j0] + a0 * sW[j0] + a1 * sW[HID + j0] + a2 * sW[2 * HID + j0] + a3 * sW[3 * HID + j0];
    float o1 = b1[j1] + a0 * sW[j1] + a1 * sW[HID + j1] + a2 * sW[2 * HID + j1] + a3 * sW[3 * HID + j1];
    g_h1[(size_t)d * HID + j0] = fmaxf(o0, 0.f);
    g_h1[(size_t)d * HID + j1] = fmaxf(o1, 0.f);
}

// -------- layer 2: aggregate 64-dim h1, 64x64 matmul, ReLU, 64->1 head --------
__global__ void k_layer2(const float* __restrict__ W2,
                         const float* __restrict__ b2,
                         const float* __restrict__ Wl,
                         const float* __restrict__ bl,
                         float* __restrict__ out) {
    __shared__ float sW2[HID * HID];     // 16 KB
    __shared__ float sAgg[8][HID];       // 8 warps/block
    int t = threadIdx.x;                 // 256 threads
    for (int i = t; i < HID * HID; i += 256) sW2[i] = W2[i];
    __syncthreads();
    int warp = (blockIdx.x * blockDim.x + t) >> 5;
    int lane = t & 31;
    int wib = t >> 5;
    if (warp >= N_NODES) return;
    int d = warp;
    int beg = g_rowoff[d], end = g_rowoff[d + 1];
    const float2* h2 = (const float2*)g_h1;
    float ax = 0.f, ay = 0.f;
    for (int i = beg; i < end; i++) {
        int s = g_csr[i];                       // broadcast load
        float w = g_dinv[s];
        float2 v = h2[(size_t)s * 32 + lane];   // 256B coalesced gather
        ax = fmaf(w, v.x, ax);
        ay = fmaf(w, v.y, ay);
    }
    float dd = g_dinv[d];
    float2 vd = h2[(size_t)d * 32 + lane];
    ax = dd * fmaf(dd, vd.x, ax);
    ay = dd * fmaf(dd, vd.y, ay);
    sAgg[wib][2 * lane] = ax;
    sAgg[wib][2 * lane + 1] = ay;
    __syncwarp();
    float o0 = b2[lane], o1 = b2[lane + 32];
#pragma unroll
    for (int k = 0; k < HID; k++) {
        float a = sAgg[wib][k];
        o0 = fmaf(a, sW2[k * HID + lane], o0);
        o1 = fmaf(a, sW2[k * HID + lane + 32], o1);
    }
    o0 = fmaxf(o0, 0.f);
    o1 = fmaxf(o1, 0.f);
    float p = o0 * Wl[lane] + o1 * Wl[lane + 32];
#pragma unroll
    for (int o = 16; o; o >>= 1) p += __shfl_xor_sync(FULL, p, o);
    if (lane == 0) out[d] = p + bl[0];
}

extern "C" void kernel_launch(void* const* d_in, const int* in_sizes, int n_in,
                              void* d_out, int out_size) {
    const float* x  = (const float*)d_in[0];
    const void*  ei = d_in[1];                 // int64 or int32, detected on device
    const float* W1 = (const float*)d_in[2];
    const float* b1 = (const float*)d_in[3];
    const float* W2 = (const float*)d_in[4];
    const float* b2 = (const float*)d_in[5];
    const float* Wl = (const float*)d_in[6];
    const float* bl = (const float*)d_in[7];
    float* out = (float*)d_out;

    (void)in_sizes; (void)n_in; (void)out_size;

    k_detect<<<1, 1024>>>(ei);
    k_zero<<<200, 512>>>();
    k_deg<<<2048, 256>>>(ei);
    k_dinv<<<200, 512>>>();
    k_scan_local<<<SCAN_BLOCKS, SCAN_CHUNK>>>();
    k_scan_top<<<1, 128>>>();
    k_scan_add<<<200, 512>>>();
    k_scatter<<<2048, 256>>>(ei);

    int blocks = (N_NODES * 32 + 255) / 256;   // warp per node
    k_layer1<<<blocks, 256>>>(x, W1, b1);
    k_layer2<<<blocks, 256>>>(W2, b2, Wl, bl, out);
}